// round 7
// baseline (speedup 1.0000x reference)
#include <cuda_runtime.h>
#include <cuda_bf16.h>
#include <stdint.h>

#define BATCH   2048
#define N0      49
#define CH      768
#define HC      384          /* channels per CTA (half) */
#define HC4     96           /* float4 columns per CTA  */
#define MID     48
#define K1      36
#define K2      24
#define THREADS 480
#define WARPS   15

// Preprocessed weights (device globals).
//   g_w1t[r][j*CH + c]  = bf16( se{r}_w1[c, j] )   transposed GEMV
//   g_w2t[r][c*MID + j] = bf16( se{r}_w2[j, c] )   transposed -> per-thread contig
//   g_clsu[o*CH + c]    = ln_gamma[c] * cls_w[c, o]
//   g_clsA[o] = sum_c ln_gamma[c]*cls_w[c,o];  g_clsB[o] = sum_c ln_beta[c]*cls_w[c,o] + cls_b[o]
__device__ __nv_bfloat16 g_w1t[2][MID * CH];
__device__ __nv_bfloat16 g_w2t[2][MID * CH];
__device__ float         g_clsu[5 * CH];
__device__ float         g_clsA[5];
__device__ float         g_clsB[5];

__global__ void convert_weights_kernel(const float* __restrict__ w1a,
                                       const float* __restrict__ w2a,
                                       const float* __restrict__ w1b,
                                       const float* __restrict__ w2b,
                                       const float* __restrict__ clsw,
                                       const float* __restrict__ lng,
                                       const float* __restrict__ lnb,
                                       const float* __restrict__ clsb) {
    int i = blockIdx.x * blockDim.x + threadIdx.x;
    if (i < MID * CH) {
        int j = i / CH;
        int c = i - j * CH;
        g_w1t[0][i] = __float2bfloat16(w1a[c * MID + j]);
        g_w1t[1][i] = __float2bfloat16(w1b[c * MID + j]);
        g_w2t[0][c * MID + j] = __float2bfloat16(w2a[j * CH + c]);
        g_w2t[1][c * MID + j] = __float2bfloat16(w2b[j * CH + c]);
    }
    if (i < 5 * CH) {
        int o = i / CH;
        int c = i - o * CH;
        g_clsu[i] = lng[c] * clsw[c * 5 + o];
    }
    if (i < 5) {
        float A = 0.f, Bv = 0.f;
        for (int c = 0; c < CH; c++) {
            A  += lng[c] * clsw[c * 5 + i];
            Bv += lnb[c] * clsw[c * 5 + i];
        }
        g_clsA[i] = A;
        g_clsB[i] = Bv + clsb[i];
    }
}

// ---------------- cluster / DSMEM helpers ----------------
__device__ __forceinline__ uint32_t smem_u32(const void* p) {
    uint32_t a;
    asm("{ .reg .u64 t; cvta.to.shared.u64 t, %1; cvt.u32.u64 %0, t; }"
        : "=r"(a) : "l"(p));
    return a;
}
__device__ __forceinline__ uint32_t my_ctarank() {
    uint32_t r;
    asm("mov.u32 %0, %%cluster_ctarank;" : "=r"(r));
    return r;
}
__device__ __forceinline__ float peer_ldf(uint32_t local_addr, uint32_t peer) {
    uint32_t ra; float v;
    asm("mapa.shared::cluster.u32 %0, %1, %2;" : "=r"(ra) : "r"(local_addr), "r"(peer));
    asm volatile("ld.shared::cluster.f32 %0, [%1];" : "=f"(v) : "r"(ra));
    return v;
}
__device__ __forceinline__ void cluster_sync() {
    asm volatile("barrier.cluster.arrive.aligned;" ::: "memory");
    asm volatile("barrier.cluster.wait.aligned;" ::: "memory");
}

// Shared memory layout (floats):
//   tile[N0*HC]=18816, part[5*HC]=1920, sbuf[HC], csum[HC], gat[HC],
//   hbuf[MID], ts[64], xh[48], xts[64], xfin[8], list[40] int, uns[16] int
#define SM_FLOATS (N0*HC + 5*HC + HC + HC + HC + MID + 64 + 48 + 64 + 8 + 40 + 16)
#define SM_BYTES  (SM_FLOATS * 4)

__global__ __launch_bounds__(THREADS, 2) __cluster_dims__(2, 1, 1)
void coatgft_kernel(const float* __restrict__ x,
                    const float* __restrict__ b1a, const float* __restrict__ b2a,
                    const float* __restrict__ b1b, const float* __restrict__ b2b,
                    float* __restrict__ out) {
    extern __shared__ float sm[];
    float* tile = sm;                    // [N0*HC]
    float* part = tile + N0 * HC;        // [5*HC]
    float* sbuf = part + 5 * HC;         // [HC]
    float* csum = sbuf + HC;             // [HC]
    float* gat  = csum + HC;             // [HC]
    float* hbuf = gat + HC;              // [MID]
    float* ts   = hbuf + MID;            // [64]
    float* xh   = ts + 64;               // [48]  exchange: h partials
    float* xts  = xh + 48;               // [64]  exchange: ts partials
    float* xfin = xts + 64;              // [8]   exchange: final 7 dots
    int*   list = (int*)(xfin + 8);      // [40]
    int*   uns  = list + 40;             // [16]

    const int tid  = threadIdx.x;
    const int lane = tid & 31;
    const int warp = tid >> 5;
    const uint32_t rank = my_ctarank();
    const uint32_t peer = rank ^ 1u;
    const int b  = blockIdx.x >> 1;
    const int hb = (int)rank * HC;       // channel base

    // ---------- fused load + round-1 column partial sums ----------
    {
        const float* xb = x + (size_t)b * N0 * CH + hb;
        const int c4 = tid % HC4;        // float4 column 0..95
        const int rb = tid / HC4;        // row group 0..4
        float4 acc = make_float4(0.f, 0.f, 0.f, 0.f);
        #pragma unroll
        for (int k = 0; k < 10; k++) {
            int r = rb + 5 * k;
            if (r < N0) {
                float4 v = *(const float4*)(xb + (size_t)r * CH + 4 * c4);
                *(float4*)(tile + r * HC + 4 * c4) = v;
                acc.x += v.x; acc.y += v.y; acc.z += v.z; acc.w += v.w;
            }
        }
        *(float4*)(part + rb * HC + 4 * c4) = acc;
    }
    __syncthreads();
    if (tid < HC) {
        float cs = part[tid] + part[HC + tid] + part[2 * HC + tid]
                 + part[3 * HC + tid] + part[4 * HC + tid];
        sbuf[tid] = cs * (1.0f / (float)N0);   // colmean
    }
    __syncthreads();

    // ================= ROUND 1 =================
    {   // h partials: up to 4 outputs per warp
        const __nv_bfloat162* W1t = (const __nv_bfloat162*)g_w1t[0];
        #pragma unroll
        for (int jj = 0; jj < 4; jj++) {
            int j = warp + jj * WARPS;
            if (j < MID) {
                const __nv_bfloat162* wr = W1t + (j * CH + hb) / 2;
                float acc = 0.f;
                #pragma unroll
                for (int k = 0; k < HC / 64; k++) {
                    int p = lane + 32 * k;
                    __nv_bfloat162 w = wr[p];
                    acc += sbuf[2 * p] * __low2float(w) + sbuf[2 * p + 1] * __high2float(w);
                }
                #pragma unroll
                for (int o = 16; o; o >>= 1) acc += __shfl_xor_sync(0xffffffffu, acc, o);
                if (lane == 0) xh[j] = acc;
            }
        }
    }
    cluster_sync();                                   // #1
    if (tid < MID) {
        float hf = xh[tid] + peer_ldf(smem_u32(&xh[tid]), peer);
        float z = hf + b1a[tid];
        hbuf[tid] = 0.5f * z * (1.0f + erff(z * 0.70710678118654752f));
    }
    __syncthreads();

    // gates1 (own channels): contiguous transposed W2 per thread
    if (tid < HC) {
        const __nv_bfloat162* w = (const __nv_bfloat162*)(g_w2t[0] + (size_t)(hb + tid) * MID);
        float acc = b2a[hb + tid];
        #pragma unroll
        for (int m = 0; m < MID / 2; m++) {
            __nv_bfloat162 wv = w[m];
            acc += hbuf[2 * m] * __low2float(wv) + hbuf[2 * m + 1] * __high2float(wv);
        }
        gat[tid] = 1.0f / (1.0f + expf(-acc));
    }
    __syncthreads();

    // ts1 partials: gates in registers, float4 tile reads
    {
        const float4* g4p = (const float4*)gat;
        float4 g0 = g4p[lane], g1 = g4p[lane + 32], g2 = g4p[lane + 64];
        #pragma unroll
        for (int ii = 0; ii < 4; ii++) {
            int r = warp + ii * WARPS;
            if (r < N0) {
                const float4* row = (const float4*)(tile + r * HC);
                float4 a = row[lane], bq = row[lane + 32], cq = row[lane + 64];
                float v, acc;
                v = a.x * g0.x; acc  = v * v;
                v = a.y * g0.y; acc += v * v;
                v = a.z * g0.z; acc += v * v;
                v = a.w * g0.w; acc += v * v;
                v = bq.x * g1.x; acc += v * v;
                v = bq.y * g1.y; acc += v * v;
                v = bq.z * g1.z; acc += v * v;
                v = bq.w * g1.w; acc += v * v;
                v = cq.x * g2.x; acc += v * v;
                v = cq.y * g2.y; acc += v * v;
                v = cq.z * g2.z; acc += v * v;
                v = cq.w * g2.w; acc += v * v;
                #pragma unroll
                for (int o = 16; o; o >>= 1) acc += __shfl_xor_sync(0xffffffffu, acc, o);
                if (lane == 0) xts[r] = acc;
            }
        }
    }
    cluster_sync();                                   // #2
    if (tid < N0)
        ts[tid] = xts[tid] + peer_ldf(smem_u32(&xts[tid]), peer);
    __syncthreads();

    // rank-select top-36; record 13 unselected
    if (tid < N0) {
        float mine = ts[tid];
        int r = 0;
        #pragma unroll
        for (int j = 0; j < N0; j++) {
            float tj = ts[j];
            r += (tj > mine) || (tj == mine && j < tid);
        }
        if (r < K1) list[r] = tid;
        else        uns[r - K1] = tid;
    }
    __syncthreads();

    // ================= ROUND 2 =================
    // csum = colsum49 - sum(13 unselected);  s2 = gat*csum/36
    if (tid < HC) {
        float cs = sbuf[tid] * (float)N0;
        #pragma unroll
        for (int i = 0; i < N0 - K1; i++) cs -= tile[uns[i] * HC + tid];
        csum[tid] = cs;
        sbuf[tid] = cs * gat[tid] * (1.0f / (float)K1);
    }
    __syncthreads();

    {
        const __nv_bfloat162* W1t = (const __nv_bfloat162*)g_w1t[1];
        #pragma unroll
        for (int jj = 0; jj < 4; jj++) {
            int j = warp + jj * WARPS;
            if (j < MID) {
                const __nv_bfloat162* wr = W1t + (j * CH + hb) / 2;
                float acc = 0.f;
                #pragma unroll
                for (int k = 0; k < HC / 64; k++) {
                    int p = lane + 32 * k;
                    __nv_bfloat162 w = wr[p];
                    acc += sbuf[2 * p] * __low2float(w) + sbuf[2 * p + 1] * __high2float(w);
                }
                #pragma unroll
                for (int o = 16; o; o >>= 1) acc += __shfl_xor_sync(0xffffffffu, acc, o);
                if (lane == 0) xh[j] = acc;
            }
        }
    }
    cluster_sync();                                   // #3
    if (tid < MID) {
        float hf = xh[tid] + peer_ldf(smem_u32(&xh[tid]), peer);
        float z = hf + b1b[tid];
        hbuf[tid] = 0.5f * z * (1.0f + erff(z * 0.70710678118654752f));
    }
    __syncthreads();

    if (tid < HC) {
        const __nv_bfloat162* w = (const __nv_bfloat162*)(g_w2t[1] + (size_t)(hb + tid) * MID);
        float acc = b2b[hb + tid];
        #pragma unroll
        for (int m = 0; m < MID / 2; m++) {
            __nv_bfloat162 wv = w[m];
            acc += hbuf[2 * m] * __low2float(wv) + hbuf[2 * m + 1] * __high2float(wv);
        }
        gat[tid] *= 1.0f / (1.0f + expf(-acc));
    }
    __syncthreads();

    // ts2 partials over the 36 selected rows (cumulative gate, regs + float4)
    {
        const float4* g4p = (const float4*)gat;
        float4 g0 = g4p[lane], g1 = g4p[lane + 32], g2 = g4p[lane + 64];
        #pragma unroll
        for (int ii = 0; ii < 3; ii++) {
            int i = warp + ii * WARPS;
            if (i < K1) {
                const float4* row = (const float4*)(tile + list[i] * HC);
                float4 a = row[lane], bq = row[lane + 32], cq = row[lane + 64];
                float v, acc;
                v = a.x * g0.x; acc  = v * v;
                v = a.y * g0.y; acc += v * v;
                v = a.z * g0.z; acc += v * v;
                v = a.w * g0.w; acc += v * v;
                v = bq.x * g1.x; acc += v * v;
                v = bq.y * g1.y; acc += v * v;
                v = bq.z * g1.z; acc += v * v;
                v = bq.w * g1.w; acc += v * v;
                v = cq.x * g2.x; acc += v * v;
                v = cq.y * g2.y; acc += v * v;
                v = cq.z * g2.z; acc += v * v;
                v = cq.w * g2.w; acc += v * v;
                #pragma unroll
                for (int o = 16; o; o >>= 1) acc += __shfl_xor_sync(0xffffffffu, acc, o);
                if (lane == 0) xts[i] = acc;
            }
        }
    }
    cluster_sync();                                   // #4
    if (tid < K1)
        ts[tid] = xts[tid] + peer_ldf(smem_u32(&xts[tid]), peer);
    __syncthreads();

    // select top-24 of 36; record 12 removed
    if (tid < K1) {
        float mine = ts[tid];
        int r = 0;
        int row = list[tid];
        #pragma unroll
        for (int j = 0; j < K1; j++) {
            float tj = ts[j];
            r += (tj > mine) || (tj == mine && j < tid);
        }
        if (r >= K2) uns[r - K2] = row;
    }
    __syncthreads();

    // pooled half = gat * (csum36 - sum(12 removed)) / 24
    if (tid < HC) {
        float cs = csum[tid];
        #pragma unroll
        for (int i = 0; i < K1 - K2; i++) cs -= tile[uns[i] * HC + tid];
        sbuf[tid] = cs * gat[tid] * (1.0f / (float)K2);
    }
    __syncthreads();

    // 7 fused reductions: D_o (o<5), S1, S2 — one warp each
    if (warp < 7) {
        float acc = 0.f;
        if (warp < 5) {
            const float* u = g_clsu + warp * CH + hb;
            #pragma unroll
            for (int k = 0; k < HC / 32; k++)
                acc += sbuf[lane + 32 * k] * u[lane + 32 * k];
        } else if (warp == 5) {
            #pragma unroll
            for (int k = 0; k < HC / 32; k++)
                acc += sbuf[lane + 32 * k];
        } else {
            #pragma unroll
            for (int k = 0; k < HC / 32; k++) {
                float v = sbuf[lane + 32 * k];
                acc += v * v;
            }
        }
        #pragma unroll
        for (int o = 16; o; o >>= 1) acc += __shfl_xor_sync(0xffffffffu, acc, o);
        if (lane == 0) xfin[warp] = acc;
    }
    cluster_sync();                                   // #5
    if (rank == 0 && tid < 5) {
        float D  = xfin[tid] + peer_ldf(smem_u32(&xfin[tid]), peer);
        float s1 = xfin[5]   + peer_ldf(smem_u32(&xfin[5]), peer);
        float s2 = xfin[6]   + peer_ldf(smem_u32(&xfin[6]), peer);
        float mu  = s1 * (1.0f / (float)CH);
        float var = s2 * (1.0f / (float)CH) - mu * mu;
        float inv = rsqrtf(var + 1e-5f);
        out[b * 5 + tid] = inv * D - inv * mu * g_clsA[tid] + g_clsB[tid];
    }
    cluster_sync();                                   // #6 keep peer smem alive
}

extern "C" void kernel_launch(void* const* d_in, const int* in_sizes, int n_in,
                              void* d_out, int out_size) {
    const float* x    = (const float*)d_in[0];
    const float* w1a  = (const float*)d_in[1];
    const float* b1a  = (const float*)d_in[2];
    const float* w2a  = (const float*)d_in[3];
    const float* b2a  = (const float*)d_in[4];
    const float* w1b  = (const float*)d_in[5];
    const float* b1b  = (const float*)d_in[6];
    const float* w2b  = (const float*)d_in[7];
    const float* b2b  = (const float*)d_in[8];
    const float* lng  = (const float*)d_in[9];
    const float* lnb  = (const float*)d_in[10];
    const float* clsw = (const float*)d_in[11];
    const float* clsb = (const float*)d_in[12];
    float* out = (float*)d_out;

    static_assert(SM_BYTES < 113000, "need 2 CTAs per SM");
    cudaFuncSetAttribute(coatgft_kernel,
                         cudaFuncAttributeMaxDynamicSharedMemorySize, SM_BYTES);

    convert_weights_kernel<<<(MID * CH + 255) / 256, 256>>>(
        w1a, w2a, w1b, w2b, clsw, lng, lnb, clsb);
    coatgft_kernel<<<2 * BATCH, THREADS, SM_BYTES>>>(x, b1a, b2a, b1b, b2b, out);
}